// round 15
// baseline (speedup 1.0000x reference)
#include <cuda_runtime.h>
#include <math.h>
#include <stdint.h>

#define BB 16
#define MM 60
#define TT 80
#define NA 128
#define NL 64
#define NP 20
#define NLP (NL*NP)        // 1280
#define NTHR 640           // 20 warps
#define SPB 8              // slices (CTAs) per batch == cluster size
#define NSTG 256           // staged lane points (fallback)
#define NJM (TT-3)         // 77 jerk norms per mode
#define TRF (MM*TT*3)      // 14400 floats per batch
#define NPF 23             // prefetch regs per thread (640*23 >= 14400)
#define BIGF 3.4e38f

__device__ __forceinline__ uint32_t smem_u32(const void* p){
    uint32_t a;
    asm("{ .reg .u64 t; cvta.to.shared.u64 t, %1; cvt.u32.u64 %0, t; }"
        : "=r"(a) : "l"(p));
    return a;
}
__device__ __forceinline__ void dsmem_store_rank0(uint32_t local_addr, float v){
    uint32_t rem;
    asm volatile("mapa.shared::cluster.u32 %0, %1, 0;" : "=r"(rem) : "r"(local_addr));
    asm volatile("st.shared::cluster.f32 [%0], %1;" :: "r"(rem), "f"(v) : "memory");
}

__global__ __launch_bounds__(NTHR) __cluster_dims__(SPB, 1, 1)
void fused_kernel(
    const float* __restrict__ mode_logits,
    const float* __restrict__ all_trajs,
    const float* __restrict__ agents_now,
    const float* __restrict__ agents_mask,
    const float* __restrict__ map_lanes,
    const float* __restrict__ lanes_mask,
    float* __restrict__ out,
    int write_idx)
{
    __shared__ __align__(16) float2 s_ag[NA];      // fallback agents
    __shared__ __align__(16) float2 s_ln[NSTG];    // fallback lane points
    __shared__ float s_jn[8*NJM];
    __shared__ float s_part[MM];
    __shared__ float s_prob[MM];
    __shared__ int   s_cc[8], s_uc[8];

    const int b    = blockIdx.x >> 3;             // batch == cluster id
    uint32_t rank;  asm("mov.u32 %0, %%cluster_ctarank;" : "=r"(rank));
    const int s    = (int)rank;
    const int MPB  = (s < 4) ? 8 : 7;
    const int m0   = (s < 4) ? s*8 : 32 + (s-4)*7;
    const int NDT  = MPB * TT;
    const int NJT  = MPB * NJM;
    const int tid  = threadIdx.x;
    const int lane = tid & 31;

    if (tid < 8){ s_cc[tid] = 0; s_uc[tid] = 0; }

    const float* trajb = all_trajs + (size_t)b * TRF;

    // ── Rank0 warp0: logits prefetch (softmax computed pre-barrier)
    float l0 = 0.0f, l1 = -BIGF;
    const bool selwarp = (rank == 0) && (tid < 32);
    if (selwarp){
        l0 = mode_logits[b*MM + lane];
        if (lane < MM-32) l1 = mode_logits[b*MM + 32 + lane];
    }

    // ── Ego + chunk-1 register prefetch (L1-broadcast, pure MLP)
    float ex = 0.0f, ey = 0.0f;
    float4 am0, am1;                   // agent masks 0..7
    float2 ag[8];                      // agent xy 0..7
    float4 lr0, lr1, lr2, lr3, lr4, lr5;   // lane floats 0..23 (8 points)
    float  lm0 = 0.0f;                 // lane mask for lane 0 (covers pts 0..19)
    if (tid < NDT){
        const float* p = trajb + (size_t)(m0*TT + tid)*3;
        ex = p[0]; ey = p[1];
        const float4* agp = (const float4*)(agents_now + (size_t)b*NA*4);
        const float4* agm = (const float4*)(agents_mask + (size_t)b*NA);
        am0 = agm[0]; am1 = agm[1];
        #pragma unroll
        for (int k = 0; k < 8; k++){
            float4 t = agp[k];
            ag[k] = make_float2(t.x, t.y);
        }
        const float4* lpt = (const float4*)(map_lanes + (size_t)b*NLP*3);
        lr0 = lpt[0]; lr1 = lpt[1]; lr2 = lpt[2];
        lr3 = lpt[3]; lr4 = lpt[4]; lr5 = lpt[5];
        lm0 = lanes_mask[b*NL];
    }

    // ── Progress prefetch
    float prog = 0.0f;
    if (tid < MPB) prog = trajb[(size_t)((m0 + tid)*TT + TT-1)*3];

    // ── Jerk prefetch (8 independent LDGs)
    int   mj = 0, tj = 0;
    float x0=0,x1=0,x2=0,x3=0, y0=0,y1=0,y2=0,y3=0;
    if (tid < NJT){
        mj = tid / NJM; tj = tid - mj*NJM;
        const float* tr = trajb + (size_t)((m0+mj)*TT + tj)*3;
        x0 = tr[0]; x1 = tr[3]; x2 = tr[6]; x3 = tr[9];
        y0 = tr[1]; y1 = tr[4]; y2 = tr[7]; y3 = tr[10];
    }

    // ── Fallback staging (overlaps the burst; rarely read)
    if (tid < NA){
        float valid = agents_mask[b*NA + tid];
        float ax = agents_now[(b*NA + tid)*4 + 0];
        float ay = agents_now[(b*NA + tid)*4 + 1];
        if (valid == 0.0f){ ax = 1e18f; ay = 0.0f; }
        s_ag[tid] = make_float2(ax, ay);
    }
    if (tid < NSTG){
        float valid = lanes_mask[b*NL + tid/NP];
        const float* src = map_lanes + ((size_t)b*NLP + tid)*3;
        float x = src[0], y = src[1];
        if (valid == 0.0f){ x = 1e18f; y = 0.0f; }
        s_ln[tid] = make_float2(x, y);
    }
    __syncthreads();

    const float4* pa = (const float4*)s_ag;
    const float4* pl = (const float4*)s_ln;

    // ── Distance tests: chunk-1 from registers; shared/global fallback (rare)
    if (tid < NDT){
        const int ml = tid / TT;

        // Agents 0..7 from registers (boolean identical to staged test)
        bool coll;
        {
            float d[8];
            #pragma unroll
            for (int k = 0; k < 8; k++){
                float dx = ex - ag[k].x, dy = ey - ag[k].y;
                d[k] = fmaf(dx, dx, dy*dy);
            }
            coll = (am0.x != 0.0f && d[0] < 4.0f) || (am0.y != 0.0f && d[1] < 4.0f)
                || (am0.z != 0.0f && d[2] < 4.0f) || (am0.w != 0.0f && d[3] < 4.0f)
                || (am1.x != 0.0f && d[4] < 4.0f) || (am1.y != 0.0f && d[5] < 4.0f)
                || (am1.z != 0.0f && d[6] < 4.0f) || (am1.w != 0.0f && d[7] < 4.0f);
            if (!coll){
                #pragma unroll 1
                for (int c = 4; c < NA/2; c += 4){      // resume at agent 8
                    float a0 = BIGF, a1 = BIGF;
                    #pragma unroll
                    for (int k = 0; k < 4; k++){
                        float4 p = pa[c+k];
                        float dx0 = ex - p.x, dy0 = ey - p.y;
                        float dx1 = ex - p.z, dy1 = ey - p.w;
                        a0 = fminf(a0, fmaf(dx0, dx0, dy0*dy0));
                        a1 = fminf(a1, fmaf(dx1, dx1, dy1*dy1));
                    }
                    if (fminf(a0, a1) < 4.0f){ coll = true; break; }
                }
            }
        }

        // Lane points 0..7 from registers (all in lane 0 -> one mask)
        bool near;
        {
            float px[8] = { lr0.x, lr0.w, lr1.z, lr2.y, lr3.x, lr3.w, lr4.z, lr5.y };
            float py[8] = { lr0.y, lr1.x, lr1.w, lr2.z, lr3.y, lr4.x, lr4.w, lr5.z };
            float mn = BIGF;
            #pragma unroll
            for (int k = 0; k < 8; k++){
                float dx = ex - px[k], dy = ey - py[k];
                mn = fminf(mn, fmaf(dx, dx, dy*dy));
            }
            near = (lm0 != 0.0f) && (mn <= 9.0f);
            if (!near){
                #pragma unroll 1
                for (int c = 4; c < NSTG/2; c += 4){    // resume at point 8
                    float n0 = BIGF, n1 = BIGF;
                    #pragma unroll
                    for (int k = 0; k < 4; k++){
                        float4 p = pl[c+k];
                        float dx0 = ex - p.x, dy0 = ey - p.y;
                        float dx1 = ex - p.z, dy1 = ey - p.w;
                        n0 = fminf(n0, fmaf(dx0, dx0, dy0*dy0));
                        n1 = fminf(n1, fmaf(dx1, dx1, dy1*dy1));
                    }
                    if (fminf(n0, n1) <= 9.0f){ near = true; break; }
                }
            }
            if (!near){                                 // exact global tail
                #pragma unroll 1
                for (int j = NSTG; j < NLP && !near; j += 8){
                    bool hit = false;
                    #pragma unroll
                    for (int k = 0; k < 8; k++){
                        int jj = j + k;
                        float mv = lanes_mask[b*NL + jj/NP];
                        const float* q = map_lanes + ((size_t)b*NLP + jj)*3;
                        float dx = ex - q[0], dy = ey - q[1];
                        if (mv != 0.0f && fmaf(dx, dx, dy*dy) <= 9.0f) hit = true;
                    }
                    if (hit) near = true;
                }
            }
        }

        if (coll)  atomicAdd(&s_cc[ml], 1);
        if (!near) atomicAdd(&s_uc[ml], 1);
    }

    // ── Jerk norm, parked in shared
    if (tid < NJT){
        float jx = x3 - 3.0f*x2 + 3.0f*x1 - x0;
        float jy = y3 - 3.0f*y2 + 3.0f*y1 - y0;
        s_jn[mj*NJM + tj] = sqrtf(jx*jx + jy*jy);
    }

    // ── Rank0 warp0: softmax precompute, parked in shared
    if (selwarp){
        float mx = fmaxf(l0, l1);
        #pragma unroll
        for (int d = 16; d; d >>= 1) mx = fmaxf(mx, __shfl_xor_sync(0xffffffffu, mx, d));
        float e0 = __expf(l0 - mx);
        float e1 = (lane < MM-32) ? __expf(l1 - mx) : 0.0f;
        float sum = e0 + e1;
        #pragma unroll
        for (int d = 16; d; d >>= 1) sum += __shfl_xor_sync(0xffffffffu, sum, d);
        sum = __shfl_sync(0xffffffffu, sum, 0);
        s_prob[lane] = e0 / sum;
        if (lane < MM-32) s_prob[32 + lane] = e1 / sum;
    }
    __syncthreads();

    // ── Per-mode partial score -> DSMEM into rank0's s_part
    if (tid < MPB){
        const int m = m0 + tid;
        const float* jrow = s_jn + tid*NJM;
        float a = 0.0f, bb2 = 0.0f, c2 = 0.0f, d2 = 0.0f;
        int i = 0;
        #pragma unroll 4
        for (; i + 3 < NJM; i += 4){
            a   += jrow[i];   bb2 += jrow[i+1];
            c2  += jrow[i+2]; d2  += jrow[i+3];
        }
        for (; i < NJM; i++) a += jrow[i];
        float js = (a + bb2) + (c2 + d2);
        float comfort   = -js / (float)NJM;
        float collision = -(float)s_cc[tid] / (float)TT;
        float drivable  = -(float)s_uc[tid] / (float)TT;
        float part = 0.1f*comfort + 0.5f*prog + 1.0f*collision + 0.3f*drivable;
        dsmem_store_rank0(smem_u32(&s_part[m]), part);
    }

    // ── Arrive first; rank0 prefetches output under the barrier shadow
    asm volatile("barrier.cluster.arrive.aligned;" ::: "memory");

    float pre[NPF];
    if (rank == 0){
        #pragma unroll
        for (int i = 0; i < NPF; i++){
            int idx = tid + i*NTHR;
            pre[i] = (idx < TRF) ? trajb[idx] : 0.0f;
        }
    }

    asm volatile("barrier.cluster.wait.aligned;" ::: "memory");
    if (rank != 0) return;

    // ── Tail: every warp computes the identical argmax (no block sync)
    float sc0 = s_prob[lane] + s_part[lane];
    float sc1 = (lane < MM-32) ? s_prob[32 + lane] + s_part[32 + lane] : -BIGF;

    float bs; int bi;
    if (sc1 > sc0){ bs = sc1; bi = lane + 32; } else { bs = sc0; bi = lane; }
    #pragma unroll
    for (int d = 16; d; d >>= 1){
        float ov = __shfl_xor_sync(0xffffffffu, bs, d);
        int   oi = __shfl_xor_sync(0xffffffffu, bi, d);
        if (ov > bs || (ov == bs && oi < bi)){ bs = ov; bi = oi; }
    }
    const int sel = __shfl_sync(0xffffffffu, bi, 0);  // first-max tie-break

    const int lo = sel * TT * 3;
    const int hi = lo + TT * 3;
    #pragma unroll
    for (int i = 0; i < NPF; i++){
        int idx = tid + i*NTHR;
        if (idx >= lo && idx < hi) out[b*TT*3 + (idx - lo)] = pre[i];
    }
    if (tid == 0 && write_idx) out[BB*TT*3 + b] = (float)sel;
}

extern "C" void kernel_launch(void* const* d_in, const int* in_sizes, int n_in,
                              void* d_out, int out_size)
{
    const float* mode_logits    = (const float*)d_in[0];
    const float* all_trajs      = (const float*)d_in[1];
    const float* agents_now     = (const float*)d_in[2];
    const float* agents_mask    = (const float*)d_in[3];
    const float* map_lanes      = (const float*)d_in[4];
    const float* map_lanes_mask = (const float*)d_in[5];
    float* out = (float*)d_out;

    int write_idx = (out_size >= BB*TT*3 + BB) ? 1 : 0;

    fused_kernel<<<BB*SPB, NTHR>>>(mode_logits, all_trajs, agents_now, agents_mask,
                                   map_lanes, map_lanes_mask, out, write_idx);
}

// round 16
// speedup vs baseline: 1.2054x; 1.2054x over previous
#include <cuda_runtime.h>
#include <math.h>
#include <stdint.h>

#define BB 16
#define MM 60
#define TT 80
#define NA 128
#define NL 64
#define NP 20
#define NLP (NL*NP)        // 1280
#define NTHR 640           // 20 warps
#define SPB 8              // slices (CTAs) per batch == cluster size
#define NSTG 256           // staged lane points
#define NJM (TT-3)         // 77 jerk norms per mode
#define TRF (MM*TT*3)      // 14400 floats per batch
#define NPF 23             // prefetch regs per thread (640*23 >= 14400)
#define BIGF 3.4e38f

__device__ __forceinline__ uint32_t smem_u32(const void* p){
    uint32_t a;
    asm("{ .reg .u64 t; cvta.to.shared.u64 t, %1; cvt.u32.u64 %0, t; }"
        : "=r"(a) : "l"(p));
    return a;
}
__device__ __forceinline__ void dsmem_store_rank0(uint32_t local_addr, float v){
    uint32_t rem;
    asm volatile("mapa.shared::cluster.u32 %0, %1, 0;" : "=r"(rem) : "r"(local_addr));
    asm volatile("st.shared::cluster.f32 [%0], %1;" :: "r"(rem), "f"(v) : "memory");
}

__global__ __launch_bounds__(NTHR) __cluster_dims__(SPB, 1, 1)
void fused_kernel(
    const float* __restrict__ mode_logits,
    const float* __restrict__ all_trajs,
    const float* __restrict__ agents_now,
    const float* __restrict__ agents_mask,
    const float* __restrict__ map_lanes,
    const float* __restrict__ lanes_mask,
    float* __restrict__ out,
    int write_idx)
{
    __shared__ __align__(16) float2 s_ag[NA];      // 1 KB
    __shared__ __align__(16) float2 s_ln[NSTG];    // 2 KB
    __shared__ float s_jn[8*NJM];                  // 2.4 KB
    __shared__ float s_part[MM];                   // rank0 receives all 60 partials
    __shared__ float s_prob[MM];                   // rank0 softmax probs (pre-barrier)
    __shared__ int   s_cc[8], s_uc[8];

    const int b    = blockIdx.x >> 3;             // batch == cluster id
    uint32_t rank;  asm("mov.u32 %0, %%cluster_ctarank;" : "=r"(rank));
    const int s    = (int)rank;                   // slice
    const int MPB  = (s < 4) ? 8 : 7;
    const int m0   = (s < 4) ? s*8 : 32 + (s-4)*7;
    const int NDT  = MPB * TT;                    // 560 or 640 scan tasks
    const int NJT  = MPB * NJM;                   // 539 or 616 jerk tasks
    const int tid  = threadIdx.x;
    const int lane = tid & 31;

    if (tid < 8){ s_cc[tid] = 0; s_uc[tid] = 0; }

    const float* trajb = all_trajs + (size_t)b * TRF;

    // ── Rank0 warp0: logits prefetch (softmax computed pre-barrier, off tail)
    float l0 = 0.0f, l1 = -BIGF;
    const bool selwarp = (rank == 0) && (tid < 32);
    if (selwarp){
        l0 = mode_logits[b*MM + lane];
        if (lane < MM-32) l1 = mode_logits[b*MM + 32 + lane];
    }

    // ── Ego prefetch (overlaps staging latency)
    float ex = 0.0f, ey = 0.0f;
    if (tid < NDT){
        const float* p = trajb + (size_t)(m0*TT + tid)*3;
        ex = p[0]; ey = p[1];
    }

    // ── Progress prefetch (removes dependent LDG from the score block)
    float prog = 0.0f;
    if (tid < MPB) prog = trajb[(size_t)((m0 + tid)*TT + TT-1)*3];

    // ── Jerk prefetch: thread owns norm (mj, tj); 8 independent LDGs (MLP)
    int   mj = 0, tj = 0;
    float x0=0,x1=0,x2=0,x3=0, y0=0,y1=0,y2=0,y3=0;
    if (tid < NJT){
        mj = tid / NJM; tj = tid - mj*NJM;
        const float* tr = trajb + (size_t)((m0+mj)*TT + tj)*3;
        x0 = tr[0]; x1 = tr[3]; x2 = tr[6]; x3 = tr[9];
        y0 = tr[1]; y1 = tr[4]; y2 = tr[7]; y3 = tr[10];
    }

    // ── Stage agents; invalid -> far away (== +BIG penalty semantics)
    if (tid < NA){
        float valid = agents_mask[b*NA + tid];
        float ax = agents_now[(b*NA + tid)*4 + 0];
        float ay = agents_now[(b*NA + tid)*4 + 1];
        if (valid == 0.0f){ ax = 1e18f; ay = 0.0f; }
        s_ag[tid] = make_float2(ax, ay);
    }
    // ── Stage first NSTG lane points (mask repeats per point)
    if (tid < NSTG){
        float valid = lanes_mask[b*NL + tid/NP];
        const float* src = map_lanes + ((size_t)b*NLP + tid)*3;
        float x = src[0], y = src[1];
        if (valid == 0.0f){ x = 1e18f; y = 0.0f; }
        s_ln[tid] = make_float2(x, y);
    }
    __syncthreads();

    const float4* pa = (const float4*)s_ag;   // 2 points per float4
    const float4* pl = (const float4*)s_ln;

    // ── Distance scans (one task per thread, shared-memory chunks)
    if (tid < NDT){
        const int ml = tid / TT;              // local mode

        bool coll = false;   // exists agent with d2 < 4       (min_dist < 2)
        bool near = false;   // exists lane point with d2 <= 9 (min_lane <= 3)

        float a0 = BIGF, a1 = BIGF;
        #pragma unroll 1
        for (int c = 0; c < NA/2; c += 4){
            #pragma unroll
            for (int k = 0; k < 4; k++){
                float4 p = pa[c+k];
                float dx0 = ex - p.x, dy0 = ey - p.y;
                float dx1 = ex - p.z, dy1 = ey - p.w;
                a0 = fminf(a0, fmaf(dx0, dx0, dy0*dy0));
                a1 = fminf(a1, fmaf(dx1, dx1, dy1*dy1));
            }
            if (fminf(a0, a1) < 4.0f){ coll = true; break; }
        }

        float n0 = BIGF, n1 = BIGF;
        #pragma unroll 1
        for (int c = 0; c < NSTG/2; c += 4){
            #pragma unroll
            for (int k = 0; k < 4; k++){
                float4 p = pl[c+k];
                float dx0 = ex - p.x, dy0 = ey - p.y;
                float dx1 = ex - p.z, dy1 = ey - p.w;
                n0 = fminf(n0, fmaf(dx0, dx0, dy0*dy0));
                n1 = fminf(n1, fmaf(dx1, dx1, dy1*dy1));
            }
            if (fminf(n0, n1) <= 9.0f){ near = true; break; }
        }
        // exact mask-aware global fallback, points NSTG..NLP-1 (statistically never)
        if (!near){
            #pragma unroll 1
            for (int j = NSTG; j < NLP && !near; j += 8){
                bool hit = false;
                #pragma unroll
                for (int k = 0; k < 8; k++){
                    int jj = j + k;
                    float mv = lanes_mask[b*NL + jj/NP];
                    const float* q = map_lanes + ((size_t)b*NLP + jj)*3;
                    float dx = ex - q[0], dy = ey - q[1];
                    if (mv != 0.0f && fmaf(dx, dx, dy*dy) <= 9.0f) hit = true;
                }
                if (hit) near = true;
            }
        }

        if (coll)  atomicAdd(&s_cc[ml], 1);   // integer -> deterministic
        if (!near) atomicAdd(&s_uc[ml], 1);
    }

    // ── Jerk norm (loads long since landed), parked in shared
    if (tid < NJT){
        float jx = x3 - 3.0f*x2 + 3.0f*x1 - x0;
        float jy = y3 - 3.0f*y2 + 3.0f*y1 - y0;
        s_jn[mj*NJM + tj] = sqrtf(jx*jx + jy*jy);
    }

    // ── Rank0 warp0: softmax precompute, parked in shared (off the tail)
    if (selwarp){
        float mx = fmaxf(l0, l1);
        #pragma unroll
        for (int d = 16; d; d >>= 1) mx = fmaxf(mx, __shfl_xor_sync(0xffffffffu, mx, d));
        float e0 = __expf(l0 - mx);
        float e1 = (lane < MM-32) ? __expf(l1 - mx) : 0.0f;
        float sum = e0 + e1;
        #pragma unroll
        for (int d = 16; d; d >>= 1) sum += __shfl_xor_sync(0xffffffffu, sum, d);
        sum = __shfl_sync(0xffffffffu, sum, 0);
        s_prob[lane] = e0 / sum;
        if (lane < MM-32) s_prob[32 + lane] = e1 / sum;
    }
    __syncthreads();

    // ── Per-mode partial score -> DSMEM store into rank0's s_part
    //    (4 interleaved accumulators: fixed association, deterministic)
    if (tid < MPB){
        const int m = m0 + tid;
        const float* jrow = s_jn + tid*NJM;
        float a = 0.0f, bb2 = 0.0f, c2 = 0.0f, d2 = 0.0f;
        int i = 0;
        #pragma unroll 4
        for (; i + 3 < NJM; i += 4){
            a   += jrow[i];   bb2 += jrow[i+1];
            c2  += jrow[i+2]; d2  += jrow[i+3];
        }
        for (; i < NJM; i++) a += jrow[i];
        float js = (a + bb2) + (c2 + d2);
        float comfort   = -js / (float)NJM;
        float collision = -(float)s_cc[tid] / (float)TT;
        float drivable  = -(float)s_uc[tid] / (float)TT;
        float part = 0.1f*comfort + 0.5f*prog + 1.0f*collision + 0.3f*drivable;
        dsmem_store_rank0(smem_u32(&s_part[m]), part);
    }

    // ── Arrive FIRST (releases DSMEM stores), THEN rank0 prefetches under
    //    the barrier shadow, then wait.
    asm volatile("barrier.cluster.arrive.aligned;" ::: "memory");

    float pre[NPF];
    if (rank == 0){
        #pragma unroll
        for (int i = 0; i < NPF; i++){
            int idx = tid + i*NTHR;
            pre[i] = (idx < TRF) ? trajb[idx] : 0.0f;
        }
    }

    asm volatile("barrier.cluster.wait.aligned;" ::: "memory");
    if (rank != 0) return;

    // ── Tail: EVERY warp computes the identical argmax (no syncthreads)
    float sc0 = s_prob[lane] + s_part[lane];
    float sc1 = (lane < MM-32) ? s_prob[32 + lane] + s_part[32 + lane] : -BIGF;

    float bs; int bi;
    if (sc1 > sc0){ bs = sc1; bi = lane + 32; } else { bs = sc0; bi = lane; }
    #pragma unroll
    for (int d = 16; d; d >>= 1){
        float ov = __shfl_xor_sync(0xffffffffu, bs, d);
        int   oi = __shfl_xor_sync(0xffffffffu, bi, d);
        if (ov > bs || (ov == bs && oi < bi)){ bs = ov; bi = oi; }
    }
    const int sel = __shfl_sync(0xffffffffu, bi, 0);  // first-max tie-break

    // ── Emit from prefetched registers: values with mode == sel
    const int lo = sel * TT * 3;
    const int hi = lo + TT * 3;
    #pragma unroll
    for (int i = 0; i < NPF; i++){
        int idx = tid + i*NTHR;
        if (idx >= lo && idx < hi) out[b*TT*3 + (idx - lo)] = pre[i];
    }
    if (tid == 0 && write_idx) out[BB*TT*3 + b] = (float)sel;
}

extern "C" void kernel_launch(void* const* d_in, const int* in_sizes, int n_in,
                              void* d_out, int out_size)
{
    const float* mode_logits    = (const float*)d_in[0];
    const float* all_trajs      = (const float*)d_in[1];
    const float* agents_now     = (const float*)d_in[2];
    const float* agents_mask    = (const float*)d_in[3];
    const float* map_lanes      = (const float*)d_in[4];
    const float* map_lanes_mask = (const float*)d_in[5];
    float* out = (float*)d_out;

    int write_idx = (out_size >= BB*TT*3 + BB) ? 1 : 0;

    fused_kernel<<<BB*SPB, NTHR>>>(mode_logits, all_trajs, agents_now, agents_mask,
                                   map_lanes, map_lanes_mask, out, write_idx);
}